// round 16
// baseline (speedup 1.0000x reference)
#include <cuda_runtime.h>
#include <cuda_fp16.h>
#include <stdint.h>
#include <math.h>

#define BB 8
#define NN 1024
#define DD 512
#define EE 8
#define NEGV (-1e9f)
#define SLOPE 0.2f

// ---------------------------------------------------------------------------
// Static device scratch (fp16 GEMM operands + oute, fp32 elsewhere)
// ---------------------------------------------------------------------------
__device__ static __half g_xh[(size_t)BB * NN * DD];      // h(x)
__device__ static __half g_wt[(size_t)EE * DD * DD];      // h(W^T) [e][z][d]
__device__ static __half g_ht[(size_t)BB * EE * DD * NN]; // h(h^T) [be][z][j]
__device__ static __half g_attn[(size_t)BB * EE * NN * NN];
__device__ static __half g_oute[(size_t)BB * EE * NN * DD];
__device__ static float  g_gate[(size_t)BB * NN * EE];
__device__ static float  g_ssrc[(size_t)BB * EE * NN];
__device__ static float  g_sdst[(size_t)BB * EE * NN];

// ---------------------------------------------------------------------------
// Helpers
// ---------------------------------------------------------------------------
__device__ __forceinline__ uint32_t smem_u32(const void* p) {
    uint32_t a;
    asm("{ .reg .u64 t; cvta.to.shared.u64 t, %1; cvt.u32.u64 %0, t; }"
        : "=r"(a) : "l"(p));
    return a;
}

#define CP16(dst, src) \
    asm volatile("cp.async.cg.shared.global [%0], [%1], 16;" :: "r"(dst), "l"(src))

#define MMA_F16(c, a0, a1, a2, a3, b0, b1) \
    asm volatile("mma.sync.aligned.m16n8k16.row.col.f32.f16.f16.f32 " \
        "{%0,%1,%2,%3}, {%4,%5,%6,%7}, {%8,%9}, {%0,%1,%2,%3};" \
        : "+f"((c)[0]), "+f"((c)[1]), "+f"((c)[2]), "+f"((c)[3]) \
        : "r"(a0), "r"(a1), "r"(a2), "r"(a3), "r"(b0), "r"(b1))

#define LDSM4(r0, r1, r2, r3, addr) \
    asm volatile("ldmatrix.sync.aligned.m8n8.x4.shared.b16 {%0,%1,%2,%3}, [%4];" \
        : "=r"(r0), "=r"(r1), "=r"(r2), "=r"(r3) : "r"(addr))

__device__ __forceinline__ uint32_t sw128(uint32_t off) {
    return off ^ ((off >> 3) & 0x70);
}

// ---------------------------------------------------------------------------
// K0b: g_wt[e][z][d] = half(W[e][d][z])
// ---------------------------------------------------------------------------
__global__ void k_tw(const float* __restrict__ W) {
    __shared__ float t[32][33];
    int e = blockIdx.z;
    int x0 = blockIdx.x * 32;
    int y0 = blockIdx.y * 32;
    int tx = threadIdx.x, ty = threadIdx.y;
    const float* Wb = W + (size_t)e * DD * DD;
#pragma unroll
    for (int i = 0; i < 32; i += 8)
        t[ty + i][tx] = Wb[(size_t)(y0 + ty + i) * DD + x0 + tx];
    __syncthreads();
    __half* Ob = g_wt + (size_t)e * DD * DD;
#pragma unroll
    for (int i = 0; i < 32; i += 8)
        Ob[(size_t)(x0 + ty + i) * DD + y0 + tx] = __float2half_rn(t[tx][ty + i]);
}

// ---------------------------------------------------------------------------
// K1: gate softmax (warp per row) + fused x -> half conversion
// ---------------------------------------------------------------------------
__global__ void k_gate(const float* __restrict__ X, const float* __restrict__ GW,
                       const float* __restrict__ GB) {
    int row = blockIdx.x * 8 + (threadIdx.x >> 5);
    int lane = threadIdx.x & 31;
    if (row >= BB * NN) return;
    float acc[EE];
#pragma unroll
    for (int e = 0; e < EE; e++) acc[e] = 0.f;
    const float* xr = X + (size_t)row * DD;
    __half* xo = g_xh + (size_t)row * DD;
    for (int d = lane; d < DD; d += 32) {
        float xv = xr[d];
        xo[d] = __float2half_rn(xv);          // fused k_cvt
        const float* gw = GW + (size_t)d * EE;
#pragma unroll
        for (int e = 0; e < EE; e++) acc[e] = fmaf(xv, gw[e], acc[e]);
    }
#pragma unroll
    for (int e = 0; e < EE; e++)
#pragma unroll
        for (int off = 16; off > 0; off >>= 1)
            acc[e] += __shfl_xor_sync(0xFFFFFFFFu, acc[e], off);
    if (lane == 0) {
        float m = -3.4e38f;
#pragma unroll
        for (int e = 0; e < EE; e++) { acc[e] += GB[e]; m = fmaxf(m, acc[e]); }
        float s = 0.f;
#pragma unroll
        for (int e = 0; e < EE; e++) { acc[e] = expf(acc[e] - m); s += acc[e]; }
        float inv = 1.0f / s;
        float* gr = g_gate + (size_t)row * EE;
#pragma unroll
        for (int e = 0; e < EE; e++) gr[e] = acc[e] * inv;
    }
}

// ---------------------------------------------------------------------------
// GEMM common tiling constants
// ---------------------------------------------------------------------------
#define BM 128
#define BN 128
#define BKH 64
#define STG_A 16384
#define STG_OFF_B 49152

// ---------------------------------------------------------------------------
// k_mma0: G1 = xh[b] @ wt[e]^T -> g_ht (transposed, half).
// 128 threads, 4 warps (2m x 2n), warp 64x64. Coalesced epilogue via smem
// transpose staging (pitch 130 halfs for bank-conflict-free column reads).
// ---------------------------------------------------------------------------
__global__ void __launch_bounds__(128, 2) k_mma0() {
    constexpr int K = DD;
    constexpr int S = K / BKH;

    extern __shared__ char smem[];
    const uint32_t sb = smem_u32(smem);

    const int tid = threadIdx.x;
    const int wid = tid >> 5;
    const int lane = tid & 31;
    const int q = lane >> 2;
    const int t4 = lane & 3;
    const int warpM = (wid & 1) * 64;
    const int warpN = (wid >> 1) * 64;

    const int l7 = lane & 7;
    const int aRow = warpM + l7 + ((lane >> 3) & 1) * 8;
    const int aCh = lane >> 4;
    const int bRow = warpN + l7 + ((lane >> 4) & 1) * 8;
    const int bCh = (lane >> 3) & 1;

    const int be = blockIdx.z;
    const int rowBase = blockIdx.y * BM;
    const int colBase = blockIdx.x * BN;

    const __half* Ab = g_xh + (size_t)(be >> 3) * NN * DD;
    const __half* Bb = g_wt + (size_t)(be & 7) * DD * DD;

    float c[4][8][4];
#pragma unroll
    for (int mi = 0; mi < 4; mi++)
#pragma unroll
        for (int ni = 0; ni < 8; ni++)
#pragma unroll
            for (int k = 0; k < 4; k++) c[mi][ni][k] = 0.f;

    auto load_stage = [&](int s) {
        const int st = s % 3;
        const uint32_t ab = sb + st * STG_A;
        const uint32_t bb = sb + STG_OFF_B + st * STG_A;
        const int k0 = s * BKH;
#pragma unroll
        for (int i = 0; i < 8; i++) {
            int id = tid + i * 128;
            int r = id >> 3;
            int ch = id & 7;
            CP16(ab + sw128((uint32_t)(r * 128 + ch * 16)),
                 Ab + (size_t)(rowBase + r) * K + k0 + ch * 8);
        }
#pragma unroll
        for (int i = 0; i < 8; i++) {
            int id = tid + i * 128;
            int r = id >> 3;
            int ch = id & 7;
            CP16(bb + sw128((uint32_t)(r * 128 + ch * 16)),
                 Bb + (size_t)(colBase + r) * K + k0 + ch * 8);
        }
        asm volatile("cp.async.commit_group;" ::: "memory");
    };

    load_stage(0);
    load_stage(1);
    for (int s = 0; s < S; s++) {
        if (s == S - 1) {
            asm volatile("cp.async.wait_group 0;" ::: "memory");
        } else {
            asm volatile("cp.async.wait_group 1;" ::: "memory");
        }
        __syncthreads();
        if (s + 2 < S) load_stage(s + 2);

        const int st = s % 3;
        const uint32_t abase = sb + st * STG_A;
        const uint32_t bbase = sb + STG_OFF_B + st * STG_A;

#pragma unroll
        for (int j = 0; j < 4; j++) {
            uint32_t bf[8][2];
#pragma unroll
            for (int nb = 0; nb < 4; nb++) {
                uint32_t addr = bbase + (uint32_t)(bRow + 16 * nb) * 128 +
                                (uint32_t)(((2 * j + bCh) ^ l7) * 16);
                LDSM4(bf[2 * nb][0], bf[2 * nb][1],
                      bf[2 * nb + 1][0], bf[2 * nb + 1][1], addr);
            }
#pragma unroll
            for (int mi = 0; mi < 4; mi++) {
                uint32_t a0, a1, a2, a3;
                uint32_t addr = abase + (uint32_t)(aRow + 16 * mi) * 128 +
                                (uint32_t)(((2 * j + aCh) ^ l7) * 16);
                LDSM4(a0, a1, a2, a3, addr);
#pragma unroll
                for (int ni = 0; ni < 8; ni++)
                    MMA_F16(c[mi][ni], a0, a1, a2, a3, bf[ni][0], bf[ni][1]);
            }
        }
    }

    // ---- epilogue: smem transpose -> coalesced half2 stores along n ----
    __half* tile = reinterpret_cast<__half*>(smem);   // [128 m][pitch 130 z]
    __syncthreads();                                  // stage buffers retired
#pragma unroll
    for (int mi = 0; mi < 4; mi++) {
        int m = warpM + 16 * mi + q;
#pragma unroll
        for (int ni = 0; ni < 8; ni++) {
            int z = warpN + 8 * ni + 2 * t4;
            tile[m * 130 + z]           = __float2half_rn(c[mi][ni][0]);
            tile[m * 130 + z + 1]       = __float2half_rn(c[mi][ni][1]);
            tile[(m + 8) * 130 + z]     = __float2half_rn(c[mi][ni][2]);
            tile[(m + 8) * 130 + z + 1] = __float2half_rn(c[mi][ni][3]);
        }
    }
    __syncthreads();
    __half* htb = g_ht + (size_t)be * DD * NN;
#pragma unroll 4
    for (int it = 0; it < 64; it++) {
        int idx = it * 128 + tid;
        int zr = idx >> 6;
        int n2 = idx & 63;
        __half2 v = __halves2half2(tile[(2 * n2) * 130 + zr],
                                   tile[(2 * n2 + 1) * 130 + zr]);
        *reinterpret_cast<__half2*>(
            &htb[(size_t)(colBase + zr) * NN + rowBase + 2 * n2]) = v;
    }
}

// ---------------------------------------------------------------------------
// k_mma1: G2 = elu(attn @ ht^T) -> g_oute (row-major, half).
// 256 threads, 8 warps (2m x 4n), warp 64x32.
// ---------------------------------------------------------------------------
__global__ void __launch_bounds__(256, 2) k_mma1() {
    constexpr int K = NN;
    constexpr int S = K / BKH;

    extern __shared__ char smem[];
    const uint32_t sb = smem_u32(smem);

    const int tid = threadIdx.x;
    const int wid = tid >> 5;
    const int lane = tid & 31;
    const int q = lane >> 2;
    const int t4 = lane & 3;
    const int warpM = (wid & 1) * 64;
    const int warpN = (wid >> 1) * 32;

    const int l7 = lane & 7;
    const int aRow = warpM + l7 + ((lane >> 3) & 1) * 8;
    const int aCh = lane >> 4;
    const int bRow = warpN + l7 + ((lane >> 4) & 1) * 8;
    const int bCh = (lane >> 3) & 1;

    const int be = blockIdx.z;
    const int rowBase = blockIdx.y * BM;
    const int colBase = blockIdx.x * BN;

    const __half* Ab = g_attn + (size_t)be * NN * NN;
    const __half* Bb = g_ht + (size_t)be * DD * NN;

    float c[4][4][4];
#pragma unroll
    for (int mi = 0; mi < 4; mi++)
#pragma unroll
        for (int ni = 0; ni < 4; ni++)
#pragma unroll
            for (int k = 0; k < 4; k++) c[mi][ni][k] = 0.f;

    auto load_stage = [&](int s) {
        const int st = s % 3;
        const uint32_t ab = sb + st * STG_A;
        const uint32_t bb = sb + STG_OFF_B + st * STG_A;
        const int k0 = s * BKH;
#pragma unroll
        for (int i = 0; i < 4; i++) {
            int id = tid + i * 256;
            int r = id >> 3;
            int ch = id & 7;
            CP16(ab + sw128((uint32_t)(r * 128 + ch * 16)),
                 Ab + (size_t)(rowBase + r) * K + k0 + ch * 8);
        }
#pragma unroll
        for (int i = 0; i < 4; i++) {
            int id = tid + i * 256;
            int r = id >> 3;
            int ch = id & 7;
            CP16(bb + sw128((uint32_t)(r * 128 + ch * 16)),
                 Bb + (size_t)(colBase + r) * K + k0 + ch * 8);
        }
        asm volatile("cp.async.commit_group;" ::: "memory");
    };

    load_stage(0);
    load_stage(1);
    for (int s = 0; s < S; s++) {
        if (s == S - 1) {
            asm volatile("cp.async.wait_group 0;" ::: "memory");
        } else {
            asm volatile("cp.async.wait_group 1;" ::: "memory");
        }
        __syncthreads();
        if (s + 2 < S) load_stage(s + 2);

        const int st = s % 3;
        const uint32_t abase = sb + st * STG_A;
        const uint32_t bbase = sb + STG_OFF_B + st * STG_A;

#pragma unroll
        for (int j = 0; j < 4; j++) {
            uint32_t bf[4][2];
#pragma unroll
            for (int nbp = 0; nbp < 2; nbp++) {
                uint32_t addr = bbase + (uint32_t)(bRow + 16 * nbp) * 128 +
                                (uint32_t)(((2 * j + bCh) ^ l7) * 16);
                LDSM4(bf[2 * nbp][0], bf[2 * nbp][1],
                      bf[2 * nbp + 1][0], bf[2 * nbp + 1][1], addr);
            }
#pragma unroll
            for (int mi = 0; mi < 4; mi++) {
                uint32_t a0, a1, a2, a3;
                uint32_t addr = abase + (uint32_t)(aRow + 16 * mi) * 128 +
                                (uint32_t)(((2 * j + aCh) ^ l7) * 16);
                LDSM4(a0, a1, a2, a3, addr);
#pragma unroll
                for (int ni = 0; ni < 4; ni++)
                    MMA_F16(c[mi][ni], a0, a1, a2, a3, bf[ni][0], bf[ni][1]);
            }
        }
    }

    __half* ob = g_oute + (size_t)be * NN * DD;
#pragma unroll
    for (int mi = 0; mi < 4; mi++) {
        int r0 = rowBase + warpM + 16 * mi + q;
#pragma unroll
        for (int ni = 0; ni < 4; ni++) {
            int c0 = colBase + warpN + 8 * ni + 2 * t4;
            float v0 = c[mi][ni][0], v1 = c[mi][ni][1];
            float v2 = c[mi][ni][2], v3 = c[mi][ni][3];
            v0 = v0 > 0.f ? v0 : expm1f(v0);
            v1 = v1 > 0.f ? v1 : expm1f(v1);
            v2 = v2 > 0.f ? v2 : expm1f(v2);
            v3 = v3 > 0.f ? v3 : expm1f(v3);
            *reinterpret_cast<__half2*>(&ob[(size_t)r0 * DD + c0]) =
                __floats2half2_rn(v0, v1);
            *reinterpret_cast<__half2*>(&ob[(size_t)(r0 + 8) * DD + c0]) =
                __floats2half2_rn(v2, v3);
        }
    }
}

// ---------------------------------------------------------------------------
// K3: scores from h^T — half2, 2 n per thread
// ---------------------------------------------------------------------------
__global__ void __launch_bounds__(256) k_scores(const float* __restrict__ ASRC,
                                                const float* __restrict__ ADST) {
    __shared__ float sa[DD], sd[DD];
    const int be = blockIdx.x >> 1;
    const int n0 = (blockIdx.x & 1) * 512;
    const int e = be & 7;
    const int tid = threadIdx.x;
    for (int z = tid; z < DD; z += 256) {
        sa[z] = ASRC[(size_t)e * DD + z];
        sd[z] = ADST[(size_t)e * DD + z];
    }
    __syncthreads();
    const __half* base = g_ht + (size_t)be * DD * NN + n0;
    float s0 = 0.f, s1 = 0.f, d0 = 0.f, d1 = 0.f;
    for (int z = 0; z < DD; z++) {
        __half2 h = reinterpret_cast<const __half2*>(base + (size_t)z * NN)[tid];
        float2 f = __half22float2(h);
        float a = sa[z], d = sd[z];
        s0 = fmaf(f.x, a, s0);
        s1 = fmaf(f.y, a, s1);
        d0 = fmaf(f.x, d, d0);
        d1 = fmaf(f.y, d, d1);
    }
    size_t o = (size_t)be * NN + n0 + 2 * tid;
    g_ssrc[o] = s0;
    g_ssrc[o + 1] = s1;
    g_sdst[o] = d0;
    g_sdst[o + 1] = d1;
}

// ---------------------------------------------------------------------------
// K4: attention softmax — register-resident scores (no sc smem)
// ---------------------------------------------------------------------------
__global__ void __launch_bounds__(256) k_attn(const int* __restrict__ ADJ) {
    const int be = blockIdx.x >> 7;
    const int i0 = (blockIdx.x & 127) * 8;
    const int b = be >> 3;
    const int tid = threadIdx.x;
    const int w = tid >> 5;
    const int lane = tid & 31;

    __shared__ float sdst[NN];
    for (int j = tid; j < NN; j += 256) sdst[j] = g_sdst[(size_t)be * NN + j];
    __syncthreads();

    const int i = i0 + w;
    const float ssrc = g_ssrc[(size_t)be * NN + i];
    const int4* adjrow4 = reinterpret_cast<const int4*>(
        ADJ + ((size_t)b * NN + i) * NN);

    float4 v[8];
    float m = -3.4e38f;
#pragma unroll
    for (int k = 0; k < 8; k++) {
        int j4 = lane + 32 * k;
        int4 a = adjrow4[j4];
        float4 sd4 = *reinterpret_cast<const float4*>(&sdst[4 * j4]);
        float s0 = ssrc + sd4.x; s0 = s0 > 0.f ? s0 : SLOPE * s0; s0 = a.x ? s0 : NEGV;
        float s1 = ssrc + sd4.y; s1 = s1 > 0.f ? s1 : SLOPE * s1; s1 = a.y ? s1 : NEGV;
        float s2 = ssrc + sd4.z; s2 = s2 > 0.f ? s2 : SLOPE * s2; s2 = a.z ? s2 : NEGV;
        float s3 = ssrc + sd4.w; s3 = s3 > 0.f ? s3 : SLOPE * s3; s3 = a.w ? s3 : NEGV;
        v[k] = make_float4(s0, s1, s2, s3);
        m = fmaxf(m, fmaxf(fmaxf(s0, s1), fmaxf(s2, s3)));
    }
#pragma unroll
    for (int off = 16; off > 0; off >>= 1)
        m = fmaxf(m, __shfl_xor_sync(0xFFFFFFFFu, m, off));

    float sum = 0.f;
#pragma unroll
    for (int k = 0; k < 8; k++) {
        v[k].x = __expf(v[k].x - m);
        v[k].y = __expf(v[k].y - m);
        v[k].z = __expf(v[k].z - m);
        v[k].w = __expf(v[k].w - m);
        sum += (v[k].x + v[k].y) + (v[k].z + v[k].w);
    }
#pragma unroll
    for (int off = 16; off > 0; off >>= 1)
        sum += __shfl_xor_sync(0xFFFFFFFFu, sum, off);

    float inv = 1.0f / sum;
    __half2* arow2 = reinterpret_cast<__half2*>(
        g_attn + ((size_t)be * NN + i) * NN);
#pragma unroll
    for (int k = 0; k < 8; k++) {
        int j4 = lane + 32 * k;
        arow2[2 * j4]     = __floats2half2_rn(v[k].x * inv, v[k].y * inv);
        arow2[2 * j4 + 1] = __floats2half2_rn(v[k].z * inv, v[k].w * inv);
    }
}

// ---------------------------------------------------------------------------
// K6: combine over experts (half oute, 4 elems/thread)
// ---------------------------------------------------------------------------
__global__ void k_combine(float* __restrict__ OUT) {
    int idx = blockIdx.x * 256 + threadIdx.x;
    const int D4 = DD / 4;
    if (idx >= BB * NN * D4) return;
    int z4 = idx % D4;
    int n = (idx / D4) % NN;
    int b = idx / (D4 * NN);

    const float* gr = g_gate + ((size_t)b * NN + n) * EE;
    float4 acc = make_float4(0.f, 0.f, 0.f, 0.f);
#pragma unroll
    for (int e = 0; e < EE; e++) {
        float g = gr[e];
        const uint2 raw = *reinterpret_cast<const uint2*>(
            g_oute + (((size_t)(b * EE + e) * NN + n) * DD) + z4 * 4);
        __half2 h0 = *reinterpret_cast<const __half2*>(&raw.x);
        __half2 h1 = *reinterpret_cast<const __half2*>(&raw.y);
        float2 f0 = __half22float2(h0);
        float2 f1 = __half22float2(h1);
        acc.x = fmaf(g, f0.x, acc.x);
        acc.y = fmaf(g, f0.y, acc.y);
        acc.z = fmaf(g, f1.x, acc.z);
        acc.w = fmaf(g, f1.y, acc.w);
    }
    reinterpret_cast<float4*>(OUT)[idx] = acc;
}

// ---------------------------------------------------------------------------
// Launch
// ---------------------------------------------------------------------------
extern "C" void kernel_launch(void* const* d_in, const int* in_sizes, int n_in,
                              void* d_out, int out_size) {
    const float* x      = (const float*)d_in[0];
    const int*   adj    = (const int*)d_in[1];
    const float* gate_W = (const float*)d_in[2];
    const float* gate_b = (const float*)d_in[3];
    const float* W      = (const float*)d_in[4];
    const float* a_src  = (const float*)d_in[5];
    const float* a_dst  = (const float*)d_in[6];
    float* out = (float*)d_out;

    const int SMEM = 98304;  // 3 stages x (16KB A + 16KB B); also covers epi tile
    cudaFuncSetAttribute(k_mma0, cudaFuncAttributeMaxDynamicSharedMemorySize, SMEM);
    cudaFuncSetAttribute(k_mma1, cudaFuncAttributeMaxDynamicSharedMemorySize, SMEM);

    k_tw<<<dim3(16, 16, 8), dim3(32, 8)>>>(W);
    k_gate<<<BB * NN / 8, 256>>>(x, gate_W, gate_b);

    k_mma0<<<dim3(DD / BN, NN / BM, BB * EE), 128, SMEM>>>();

    k_scores<<<64 * 2, 256>>>(a_src, a_dst);
    k_attn<<<BB * EE * (NN / 8), 256>>>(adj);

    k_mma1<<<dim3(DD / BN, NN / BM, BB * EE), 256, SMEM>>>();

    k_combine<<<(BB * NN * (DD / 4) + 255) / 256, 256>>>(out);
}

// round 17
// speedup vs baseline: 1.0457x; 1.0457x over previous
#include <cuda_runtime.h>
#include <cuda_fp16.h>
#include <stdint.h>
#include <math.h>

#define BB 8
#define NN 1024
#define DD 512
#define EE 8
#define NEGV (-1e9f)
#define SLOPE 0.2f

// ---------------------------------------------------------------------------
// Static device scratch (fp16 GEMM operands + oute, fp32 elsewhere)
// ---------------------------------------------------------------------------
__device__ static __half g_xh[(size_t)BB * NN * DD];      // h(x)
__device__ static __half g_wt[(size_t)EE * DD * DD];      // h(W^T) [e][z][d]
__device__ static __half g_ht[(size_t)BB * EE * DD * NN]; // h(h^T) [be][z][j]
__device__ static __half g_attn[(size_t)BB * EE * NN * NN];
__device__ static __half g_oute[(size_t)BB * EE * NN * DD];
__device__ static float  g_gate[(size_t)BB * NN * EE];
__device__ static float  g_ssrc[(size_t)BB * EE * NN];
__device__ static float  g_sdst[(size_t)BB * EE * NN];

// ---------------------------------------------------------------------------
// Helpers
// ---------------------------------------------------------------------------
__device__ __forceinline__ uint32_t smem_u32(const void* p) {
    uint32_t a;
    asm("{ .reg .u64 t; cvta.to.shared.u64 t, %1; cvt.u32.u64 %0, t; }"
        : "=r"(a) : "l"(p));
    return a;
}

#define CP16(dst, src) \
    asm volatile("cp.async.cg.shared.global [%0], [%1], 16;" :: "r"(dst), "l"(src))

#define MMA_F16(c, a0, a1, a2, a3, b0, b1) \
    asm volatile("mma.sync.aligned.m16n8k16.row.col.f32.f16.f16.f32 " \
        "{%0,%1,%2,%3}, {%4,%5,%6,%7}, {%8,%9}, {%0,%1,%2,%3};" \
        : "+f"((c)[0]), "+f"((c)[1]), "+f"((c)[2]), "+f"((c)[3]) \
        : "r"(a0), "r"(a1), "r"(a2), "r"(a3), "r"(b0), "r"(b1))

#define LDSM4(r0, r1, r2, r3, addr) \
    asm volatile("ldmatrix.sync.aligned.m8n8.x4.shared.b16 {%0,%1,%2,%3}, [%4];" \
        : "=r"(r0), "=r"(r1), "=r"(r2), "=r"(r3) : "r"(addr))

__device__ __forceinline__ uint32_t sw128(uint32_t off) {
    return off ^ ((off >> 3) & 0x70);
}

// ---------------------------------------------------------------------------
// K0b: g_wt[e][z][d] = half(W[e][d][z])
// ---------------------------------------------------------------------------
__global__ void k_tw(const float* __restrict__ W) {
    __shared__ float t[32][33];
    int e = blockIdx.z;
    int x0 = blockIdx.x * 32;
    int y0 = blockIdx.y * 32;
    int tx = threadIdx.x, ty = threadIdx.y;
    const float* Wb = W + (size_t)e * DD * DD;
#pragma unroll
    for (int i = 0; i < 32; i += 8)
        t[ty + i][tx] = Wb[(size_t)(y0 + ty + i) * DD + x0 + tx];
    __syncthreads();
    __half* Ob = g_wt + (size_t)e * DD * DD;
#pragma unroll
    for (int i = 0; i < 32; i += 8)
        Ob[(size_t)(x0 + ty + i) * DD + y0 + tx] = __float2half_rn(t[tx][ty + i]);
}

// ---------------------------------------------------------------------------
// K1: gate softmax (warp per row) + fused x -> half conversion
// ---------------------------------------------------------------------------
__global__ void k_gate(const float* __restrict__ X, const float* __restrict__ GW,
                       const float* __restrict__ GB) {
    int row = blockIdx.x * 8 + (threadIdx.x >> 5);
    int lane = threadIdx.x & 31;
    if (row >= BB * NN) return;
    float acc[EE];
#pragma unroll
    for (int e = 0; e < EE; e++) acc[e] = 0.f;
    const float* xr = X + (size_t)row * DD;
    __half* xo = g_xh + (size_t)row * DD;
    for (int d = lane; d < DD; d += 32) {
        float xv = xr[d];
        xo[d] = __float2half_rn(xv);          // fused k_cvt
        const float* gw = GW + (size_t)d * EE;
#pragma unroll
        for (int e = 0; e < EE; e++) acc[e] = fmaf(xv, gw[e], acc[e]);
    }
#pragma unroll
    for (int e = 0; e < EE; e++)
#pragma unroll
        for (int off = 16; off > 0; off >>= 1)
            acc[e] += __shfl_xor_sync(0xFFFFFFFFu, acc[e], off);
    if (lane == 0) {
        float m = -3.4e38f;
#pragma unroll
        for (int e = 0; e < EE; e++) { acc[e] += GB[e]; m = fmaxf(m, acc[e]); }
        float s = 0.f;
#pragma unroll
        for (int e = 0; e < EE; e++) { acc[e] = expf(acc[e] - m); s += acc[e]; }
        float inv = 1.0f / s;
        float* gr = g_gate + (size_t)row * EE;
#pragma unroll
        for (int e = 0; e < EE; e++) gr[e] = acc[e] * inv;
    }
}

// ---------------------------------------------------------------------------
// GEMM common tiling constants
// ---------------------------------------------------------------------------
#define BM 128
#define BN 128
#define BKH 64
#define STG_A 16384
#define STG_OFF_B 49152

// ---------------------------------------------------------------------------
// k_mma0: G1 = xh[b] @ wt[e]^T -> g_ht (transposed, half).
// 128 threads, 4 warps (2m x 2n), warp 64x64. Coalesced epilogue via smem
// transpose staging (pitch 130 halfs for bank-conflict-free column reads).
// ---------------------------------------------------------------------------
__global__ void __launch_bounds__(128, 2) k_mma0() {
    constexpr int K = DD;
    constexpr int S = K / BKH;

    extern __shared__ char smem[];
    const uint32_t sb = smem_u32(smem);

    const int tid = threadIdx.x;
    const int wid = tid >> 5;
    const int lane = tid & 31;
    const int q = lane >> 2;
    const int t4 = lane & 3;
    const int warpM = (wid & 1) * 64;
    const int warpN = (wid >> 1) * 64;

    const int l7 = lane & 7;
    const int aRow = warpM + l7 + ((lane >> 3) & 1) * 8;
    const int aCh = lane >> 4;
    const int bRow = warpN + l7 + ((lane >> 4) & 1) * 8;
    const int bCh = (lane >> 3) & 1;

    const int be = blockIdx.z;
    const int rowBase = blockIdx.y * BM;
    const int colBase = blockIdx.x * BN;

    const __half* Ab = g_xh + (size_t)(be >> 3) * NN * DD;
    const __half* Bb = g_wt + (size_t)(be & 7) * DD * DD;

    float c[4][8][4];
#pragma unroll
    for (int mi = 0; mi < 4; mi++)
#pragma unroll
        for (int ni = 0; ni < 8; ni++)
#pragma unroll
            for (int k = 0; k < 4; k++) c[mi][ni][k] = 0.f;

    auto load_stage = [&](int s) {
        const int st = s % 3;
        const uint32_t ab = sb + st * STG_A;
        const uint32_t bb = sb + STG_OFF_B + st * STG_A;
        const int k0 = s * BKH;
#pragma unroll
        for (int i = 0; i < 8; i++) {
            int id = tid + i * 128;
            int r = id >> 3;
            int ch = id & 7;
            CP16(ab + sw128((uint32_t)(r * 128 + ch * 16)),
                 Ab + (size_t)(rowBase + r) * K + k0 + ch * 8);
        }
#pragma unroll
        for (int i = 0; i < 8; i++) {
            int id = tid + i * 128;
            int r = id >> 3;
            int ch = id & 7;
            CP16(bb + sw128((uint32_t)(r * 128 + ch * 16)),
                 Bb + (size_t)(colBase + r) * K + k0 + ch * 8);
        }
        asm volatile("cp.async.commit_group;" ::: "memory");
    };

    load_stage(0);
    load_stage(1);
    for (int s = 0; s < S; s++) {
        if (s == S - 1) {
            asm volatile("cp.async.wait_group 0;" ::: "memory");
        } else {
            asm volatile("cp.async.wait_group 1;" ::: "memory");
        }
        __syncthreads();
        if (s + 2 < S) load_stage(s + 2);

        const int st = s % 3;
        const uint32_t abase = sb + st * STG_A;
        const uint32_t bbase = sb + STG_OFF_B + st * STG_A;

#pragma unroll
        for (int j = 0; j < 4; j++) {
            uint32_t bf[8][2];
#pragma unroll
            for (int nb = 0; nb < 4; nb++) {
                uint32_t addr = bbase + (uint32_t)(bRow + 16 * nb) * 128 +
                                (uint32_t)(((2 * j + bCh) ^ l7) * 16);
                LDSM4(bf[2 * nb][0], bf[2 * nb][1],
                      bf[2 * nb + 1][0], bf[2 * nb + 1][1], addr);
            }
#pragma unroll
            for (int mi = 0; mi < 4; mi++) {
                uint32_t a0, a1, a2, a3;
                uint32_t addr = abase + (uint32_t)(aRow + 16 * mi) * 128 +
                                (uint32_t)(((2 * j + aCh) ^ l7) * 16);
                LDSM4(a0, a1, a2, a3, addr);
#pragma unroll
                for (int ni = 0; ni < 8; ni++)
                    MMA_F16(c[mi][ni], a0, a1, a2, a3, bf[ni][0], bf[ni][1]);
            }
        }
    }

    // ---- epilogue: smem transpose -> coalesced half2 stores along n ----
    __half* tile = reinterpret_cast<__half*>(smem);   // [128 m][pitch 130 z]
    __syncthreads();                                  // stage buffers retired
#pragma unroll
    for (int mi = 0; mi < 4; mi++) {
        int m = warpM + 16 * mi + q;
#pragma unroll
        for (int ni = 0; ni < 8; ni++) {
            int z = warpN + 8 * ni + 2 * t4;
            tile[m * 130 + z]           = __float2half_rn(c[mi][ni][0]);
            tile[m * 130 + z + 1]       = __float2half_rn(c[mi][ni][1]);
            tile[(m + 8) * 130 + z]     = __float2half_rn(c[mi][ni][2]);
            tile[(m + 8) * 130 + z + 1] = __float2half_rn(c[mi][ni][3]);
        }
    }
    __syncthreads();
    __half* htb = g_ht + (size_t)be * DD * NN;
#pragma unroll 4
    for (int it = 0; it < 64; it++) {
        int idx = it * 128 + tid;
        int zr = idx >> 6;
        int n2 = idx & 63;
        __half2 v = __halves2half2(tile[(2 * n2) * 130 + zr],
                                   tile[(2 * n2 + 1) * 130 + zr]);
        *reinterpret_cast<__half2*>(
            &htb[(size_t)(colBase + zr) * NN + rowBase + 2 * n2]) = v;
    }
}

// ---------------------------------------------------------------------------
// k_mma1: G2 = elu(attn @ ht^T) -> g_oute (row-major, half).
// 256 threads, 8 warps (2m x 4n), warp 64x32.
// ---------------------------------------------------------------------------
__global__ void __launch_bounds__(256, 2) k_mma1() {
    constexpr int K = NN;
    constexpr int S = K / BKH;

    extern __shared__ char smem[];
    const uint32_t sb = smem_u32(smem);

    const int tid = threadIdx.x;
    const int wid = tid >> 5;
    const int lane = tid & 31;
    const int q = lane >> 2;
    const int t4 = lane & 3;
    const int warpM = (wid & 1) * 64;
    const int warpN = (wid >> 1) * 32;

    const int l7 = lane & 7;
    const int aRow = warpM + l7 + ((lane >> 3) & 1) * 8;
    const int aCh = lane >> 4;
    const int bRow = warpN + l7 + ((lane >> 4) & 1) * 8;
    const int bCh = (lane >> 3) & 1;

    const int be = blockIdx.z;
    const int rowBase = blockIdx.y * BM;
    const int colBase = blockIdx.x * BN;

    const __half* Ab = g_attn + (size_t)be * NN * NN;
    const __half* Bb = g_ht + (size_t)be * DD * NN;

    float c[4][4][4];
#pragma unroll
    for (int mi = 0; mi < 4; mi++)
#pragma unroll
        for (int ni = 0; ni < 4; ni++)
#pragma unroll
            for (int k = 0; k < 4; k++) c[mi][ni][k] = 0.f;

    auto load_stage = [&](int s) {
        const int st = s % 3;
        const uint32_t ab = sb + st * STG_A;
        const uint32_t bb = sb + STG_OFF_B + st * STG_A;
        const int k0 = s * BKH;
#pragma unroll
        for (int i = 0; i < 4; i++) {
            int id = tid + i * 256;
            int r = id >> 3;
            int ch = id & 7;
            CP16(ab + sw128((uint32_t)(r * 128 + ch * 16)),
                 Ab + (size_t)(rowBase + r) * K + k0 + ch * 8);
        }
#pragma unroll
        for (int i = 0; i < 4; i++) {
            int id = tid + i * 256;
            int r = id >> 3;
            int ch = id & 7;
            CP16(bb + sw128((uint32_t)(r * 128 + ch * 16)),
                 Bb + (size_t)(colBase + r) * K + k0 + ch * 8);
        }
        asm volatile("cp.async.commit_group;" ::: "memory");
    };

    load_stage(0);
    load_stage(1);
    for (int s = 0; s < S; s++) {
        if (s == S - 1) {
            asm volatile("cp.async.wait_group 0;" ::: "memory");
        } else {
            asm volatile("cp.async.wait_group 1;" ::: "memory");
        }
        __syncthreads();
        if (s + 2 < S) load_stage(s + 2);

        const int st = s % 3;
        const uint32_t abase = sb + st * STG_A;
        const uint32_t bbase = sb + STG_OFF_B + st * STG_A;

#pragma unroll
        for (int j = 0; j < 4; j++) {
            uint32_t bf[4][2];
#pragma unroll
            for (int nbp = 0; nbp < 2; nbp++) {
                uint32_t addr = bbase + (uint32_t)(bRow + 16 * nbp) * 128 +
                                (uint32_t)(((2 * j + bCh) ^ l7) * 16);
                LDSM4(bf[2 * nbp][0], bf[2 * nbp][1],
                      bf[2 * nbp + 1][0], bf[2 * nbp + 1][1], addr);
            }
#pragma unroll
            for (int mi = 0; mi < 4; mi++) {
                uint32_t a0, a1, a2, a3;
                uint32_t addr = abase + (uint32_t)(aRow + 16 * mi) * 128 +
                                (uint32_t)(((2 * j + aCh) ^ l7) * 16);
                LDSM4(a0, a1, a2, a3, addr);
#pragma unroll
                for (int ni = 0; ni < 4; ni++)
                    MMA_F16(c[mi][ni], a0, a1, a2, a3, bf[ni][0], bf[ni][1]);
            }
        }
    }

    __half* ob = g_oute + (size_t)be * NN * DD;
#pragma unroll
    for (int mi = 0; mi < 4; mi++) {
        int r0 = rowBase + warpM + 16 * mi + q;
#pragma unroll
        for (int ni = 0; ni < 4; ni++) {
            int c0 = colBase + warpN + 8 * ni + 2 * t4;
            float v0 = c[mi][ni][0], v1 = c[mi][ni][1];
            float v2 = c[mi][ni][2], v3 = c[mi][ni][3];
            v0 = v0 > 0.f ? v0 : expm1f(v0);
            v1 = v1 > 0.f ? v1 : expm1f(v1);
            v2 = v2 > 0.f ? v2 : expm1f(v2);
            v3 = v3 > 0.f ? v3 : expm1f(v3);
            *reinterpret_cast<__half2*>(&ob[(size_t)r0 * DD + c0]) =
                __floats2half2_rn(v0, v1);
            *reinterpret_cast<__half2*>(&ob[(size_t)(r0 + 8) * DD + c0]) =
                __floats2half2_rn(v2, v3);
        }
    }
}

// ---------------------------------------------------------------------------
// K3: scores from h^T — 512 blocks, 4-way z-parallel partials + smem reduce
// ---------------------------------------------------------------------------
__global__ void __launch_bounds__(256) k_scores(const float* __restrict__ ASRC,
                                                const float* __restrict__ ADST) {
    __shared__ float sa[DD], sd[DD];
    __shared__ float red[4][64][4];

    const int be = blockIdx.x >> 3;
    const int n0 = (blockIdx.x & 7) * 128;      // 128 n per block (64 half2)
    const int e = be & 7;
    const int tid = threadIdx.x;
    const int tx = tid & 63;                     // half2 column
    const int ty = tid >> 6;                     // z-quarter 0..3

    for (int z = tid; z < DD; z += 256) {
        sa[z] = ASRC[(size_t)e * DD + z];
        sd[z] = ADST[(size_t)e * DD + z];
    }
    __syncthreads();

    const __half* base = g_ht + (size_t)be * DD * NN + n0;
    float s0 = 0.f, s1 = 0.f, d0 = 0.f, d1 = 0.f;
    const int z0 = ty * 128;
#pragma unroll 4
    for (int zi = 0; zi < 128; zi++) {
        int z = z0 + zi;
        __half2 h = reinterpret_cast<const __half2*>(base + (size_t)z * NN)[tx];
        float2 f = __half22float2(h);
        float a = sa[z], d = sd[z];
        s0 = fmaf(f.x, a, s0);
        s1 = fmaf(f.y, a, s1);
        d0 = fmaf(f.x, d, d0);
        d1 = fmaf(f.y, d, d1);
    }
    red[ty][tx][0] = s0;
    red[ty][tx][1] = s1;
    red[ty][tx][2] = d0;
    red[ty][tx][3] = d1;
    __syncthreads();

    if (ty == 0) {
        float r0 = 0.f, r1 = 0.f, r2 = 0.f, r3 = 0.f;
#pragma unroll
        for (int g = 0; g < 4; g++) {
            r0 += red[g][tx][0];
            r1 += red[g][tx][1];
            r2 += red[g][tx][2];
            r3 += red[g][tx][3];
        }
        size_t o = (size_t)be * NN + n0 + 2 * tx;
        g_ssrc[o] = r0;
        g_ssrc[o + 1] = r1;
        g_sdst[o] = r2;
        g_sdst[o + 1] = r3;
    }
}

// ---------------------------------------------------------------------------
// K4: attention softmax — register-resident scores (no sc smem)
// ---------------------------------------------------------------------------
__global__ void __launch_bounds__(256) k_attn(const int* __restrict__ ADJ) {
    const int be = blockIdx.x >> 7;
    const int i0 = (blockIdx.x & 127) * 8;
    const int b = be >> 3;
    const int tid = threadIdx.x;
    const int w = tid >> 5;
    const int lane = tid & 31;

    __shared__ float sdst[NN];
    for (int j = tid; j < NN; j += 256) sdst[j] = g_sdst[(size_t)be * NN + j];
    __syncthreads();

    const int i = i0 + w;
    const float ssrc = g_ssrc[(size_t)be * NN + i];
    const int4* adjrow4 = reinterpret_cast<const int4*>(
        ADJ + ((size_t)b * NN + i) * NN);

    float4 v[8];
    float m = -3.4e38f;
#pragma unroll
    for (int k = 0; k < 8; k++) {
        int j4 = lane + 32 * k;
        int4 a = adjrow4[j4];
        float4 sd4 = *reinterpret_cast<const float4*>(&sdst[4 * j4]);
        float s0 = ssrc + sd4.x; s0 = s0 > 0.f ? s0 : SLOPE * s0; s0 = a.x ? s0 : NEGV;
        float s1 = ssrc + sd4.y; s1 = s1 > 0.f ? s1 : SLOPE * s1; s1 = a.y ? s1 : NEGV;
        float s2 = ssrc + sd4.z; s2 = s2 > 0.f ? s2 : SLOPE * s2; s2 = a.z ? s2 : NEGV;
        float s3 = ssrc + sd4.w; s3 = s3 > 0.f ? s3 : SLOPE * s3; s3 = a.w ? s3 : NEGV;
        v[k] = make_float4(s0, s1, s2, s3);
        m = fmaxf(m, fmaxf(fmaxf(s0, s1), fmaxf(s2, s3)));
    }
#pragma unroll
    for (int off = 16; off > 0; off >>= 1)
        m = fmaxf(m, __shfl_xor_sync(0xFFFFFFFFu, m, off));

    float sum = 0.f;
#pragma unroll
    for (int k = 0; k < 8; k++) {
        v[k].x = __expf(v[k].x - m);
        v[k].y = __expf(v[k].y - m);
        v[k].z = __expf(v[k].z - m);
        v[k].w = __expf(v[k].w - m);
        sum += (v[k].x + v[k].y) + (v[k].z + v[k].w);
    }
#pragma unroll
    for (int off = 16; off > 0; off >>= 1)
        sum += __shfl_xor_sync(0xFFFFFFFFu, sum, off);

    float inv = 1.0f / sum;
    __half2* arow2 = reinterpret_cast<__half2*>(
        g_attn + ((size_t)be * NN + i) * NN);
#pragma unroll
    for (int k = 0; k < 8; k++) {
        int j4 = lane + 32 * k;
        arow2[2 * j4]     = __floats2half2_rn(v[k].x * inv, v[k].y * inv);
        arow2[2 * j4 + 1] = __floats2half2_rn(v[k].z * inv, v[k].w * inv);
    }
}

// ---------------------------------------------------------------------------
// K6: combine over experts (half oute, 4 elems/thread)
// ---------------------------------------------------------------------------
__global__ void k_combine(float* __restrict__ OUT) {
    int idx = blockIdx.x * 256 + threadIdx.x;
    const int D4 = DD / 4;
    if (idx >= BB * NN * D4) return;
    int z4 = idx % D4;
    int n = (idx / D4) % NN;
    int b = idx / (D4 * NN);

    const float* gr = g_gate + ((size_t)b * NN + n) * EE;
    float4 acc = make_float4(0.f, 0.f, 0.f, 0.f);
#pragma unroll
    for (int e = 0; e < EE; e++) {
        float g = gr[e];
        const uint2 raw = *reinterpret_cast<const uint2*>(
            g_oute + (((size_t)(b * EE + e) * NN + n) * DD) + z4 * 4);
        __half2 h0 = *reinterpret_cast<const __half2*>(&raw.x);
        __half2 h1 = *reinterpret_cast<const __half2*>(&raw.y);
        float2 f0 = __half22float2(h0);
        float2 f1 = __half22float2(h1);
        acc.x = fmaf(g, f0.x, acc.x);
        acc.y = fmaf(g, f0.y, acc.y);
        acc.z = fmaf(g, f1.x, acc.z);
        acc.w = fmaf(g, f1.y, acc.w);
    }
    reinterpret_cast<float4*>(OUT)[idx] = acc;
}

// ---------------------------------------------------------------------------
// Launch
// ---------------------------------------------------------------------------
extern "C" void kernel_launch(void* const* d_in, const int* in_sizes, int n_in,
                              void* d_out, int out_size) {
    const float* x      = (const float*)d_in[0];
    const int*   adj    = (const int*)d_in[1];
    const float* gate_W = (const float*)d_in[2];
    const float* gate_b = (const float*)d_in[3];
    const float* W      = (const float*)d_in[4];
    const float* a_src  = (const float*)d_in[5];
    const float* a_dst  = (const float*)d_in[6];
    float* out = (float*)d_out;

    const int SMEM = 98304;  // 3 stages x (16KB A + 16KB B); also covers epi tile
    cudaFuncSetAttribute(k_mma0, cudaFuncAttributeMaxDynamicSharedMemorySize, SMEM);
    cudaFuncSetAttribute(k_mma1, cudaFuncAttributeMaxDynamicSharedMemorySize, SMEM);

    k_tw<<<dim3(16, 16, 8), dim3(32, 8)>>>(W);
    k_gate<<<BB * NN / 8, 256>>>(x, gate_W, gate_b);

    k_mma0<<<dim3(DD / BN, NN / BM, BB * EE), 128, SMEM>>>();

    k_scores<<<64 * 8, 256>>>(a_src, a_dst);
    k_attn<<<BB * EE * (NN / 8), 256>>>(adj);

    k_mma1<<<dim3(DD / BN, NN / BM, BB * EE), 256, SMEM>>>();

    k_combine<<<(BB * NN * (DD / 4) + 255) / 256, 256>>>(out);
}